// round 9
// baseline (speedup 1.0000x reference)
#include <cuda_runtime.h>
#include <cuda_fp16.h>
#include <math.h>

#define BB 2
#define CC 256
#define HH 200
#define WW 304
#define HW (HH * WW)            /* 60800 = 64 * 950 exactly */
#define OUTH 7
#define OUTW 7
#define NBINS (OUTH * OUTW)
#define SRR 2
#define SCALE 0.25f
#define NLOC 28                 /* samples needed by one block: 7 bins x 4 */

// NHWC fp16 scratch as uint2 so 8-byte gathers are guaranteed aligned.
// (B, H, W, C) halves = 62.3 MB (L2-resident).
__device__ uint2 g_nhwc2[(size_t)BB * HW * (CC / 4)];

// ---------------------------------------------------------------------------
// Kernel 1: NCHW f32 -> NHWC fp16. Tile 64 ch x 64 hw, 256 threads.
// HW = 64*950 exactly -> no bounds checks. float4 global reads (LDG.128),
// uint4 packed writes (8 channels = 16B). Pad-65 smem: write-phase column
// reads are at worst 2-way bank conflicted.
// ---------------------------------------------------------------------------
__global__ __launch_bounds__(256) void nchw_to_nhwc_h(const float* __restrict__ in) {
    __shared__ float tile[64 * 65];
    const int b   = blockIdx.z;
    const int hw0 = blockIdx.x * 64;
    const int c0  = blockIdx.y * 64;
    const int t   = threadIdx.x;       // 0..255

    // read phase: thread handles float4 x = t&15, rows c = (t>>4) + 16*i
    const int x  = t & 15;             // 16 float4 = 64 hw
    const int cr = t >> 4;             // 0..15
    const float* src = in + (size_t)b * CC * HW + (size_t)(c0 + cr) * HW + hw0 + 4 * x;
#pragma unroll
    for (int i = 0; i < 4; i++) {
        float4 v = *(const float4*)(src + (size_t)(16 * i) * HW);
        float* dst = &tile[(cr + 16 * i) * 65 + 4 * x];
        dst[0] = v.x; dst[1] = v.y; dst[2] = v.z; dst[3] = v.w;
    }
    __syncthreads();

    // write phase: 512 uint4 (8 ch each); thread does w = t and t + 256
    __half2* outh = (__half2*)g_nhwc2 + (size_t)b * HW * (CC / 2);
#pragma unroll
    for (int i = 0; i < 2; i++) {
        int w  = t + 256 * i;
        int hw = w >> 3;               // 0..63
        int cg = w & 7;                // 8-channel group
        const float* col = &tile[(cg * 8) * 65 + hw];
        uint4 pk;
        __half2 h;
        h = __floats2half2_rn(col[0 * 65], col[1 * 65]); pk.x = *(unsigned*)&h;
        h = __floats2half2_rn(col[2 * 65], col[3 * 65]); pk.y = *(unsigned*)&h;
        h = __floats2half2_rn(col[4 * 65], col[5 * 65]); pk.z = *(unsigned*)&h;
        h = __floats2half2_rn(col[6 * 65], col[7 * 65]); pk.w = *(unsigned*)&h;
        *(uint4*)(outh + ((size_t)(hw0 + hw) * CC + c0) / 2 + cg * 4) = pk;
    }
}

// ---------------------------------------------------------------------------
// Kernel 2: rotated ROI align on fp16 NHWC.
// Grid (n_rois, 7), block = 64 threads = ONE 7-bin chunk (no idle subgroups).
// Setup computes only the 28 samples this block needs (__sincosf fast path).
// 4 ch/thread via uint2 (8B) gathers, f32 FMA inner loop (R7's proven best),
// fp16 stage, coalesced f32 flush. ~4.7KB smem, 24 blocks/SM.
// ---------------------------------------------------------------------------
#define TPB 64

struct AlignSmem {
    int4   o[NLOC];              // 4 corner offsets in uint2 units (pix*64)
    float4 w[NLOC];              // 4 bilinear weights (zeroed if empty)
    __half stage[7][264];        // [bin-in-chunk][channel(+pad)]
    int    base_b;
};

__global__ __launch_bounds__(TPB, 24) void roi_align_rotated(
    const float* __restrict__ rois, float* __restrict__ out) {
    __shared__ AlignSmem sm;
    const int n   = blockIdx.x;
    const int tid = threadIdx.x;      // 0..63 = channel-group lane
    const float* r = rois + (size_t)n * 6;
    const int b0  = 7 * blockIdx.y;   // chunk base bin

    if (tid < NLOC) {
        // local sample t -> (bin-in-chunk, iy, ix)
        const int bi = tid >> 2;
        const int iy = (tid >> 1) & 1;
        const int ix = tid & 1;
        const int bin = b0 + bi;
        const int ph  = bin / OUTW;
        const int pw  = bin - ph * OUTW;
        const int i = ph * SRR + iy;      // y sample index
        const int j = pw * SRR + ix;      // x sample index

        float cw = r[1] * SCALE - 0.5f;
        float ch = r[2] * SCALE - 0.5f;
        float rw = r[3] * SCALE;
        float rh = r[4] * SCALE;
        float theta = r[5] * (float)(M_PI / 180.0);
        float st, ct;
        __sincosf(theta, &st, &ct);

        float bin_h = rh * (1.0f / OUTH);
        float bin_w = rw * (1.0f / OUTW);
        float ty = (i + 0.5f) * (1.0f / SRR);
        float tx = (j + 0.5f) * (1.0f / SRR);
        float yy = -rh * 0.5f + ty * bin_h;
        float xx = -rw * 0.5f + tx * bin_w;
        float y = yy * ct - xx * st + ch;
        float x = yy * st + xx * ct + cw;

        bool empty = (y < -1.0f) | (y > (float)HH) | (x < -1.0f) | (x > (float)WW);
        y = fmaxf(y, 0.0f);
        x = fmaxf(x, 0.0f);
        int yl = min((int)floorf(y), HH - 1);
        int xl = min((int)floorf(x), WW - 1);
        int yh = min(yl + 1, HH - 1);
        int xh = min(xl + 1, WW - 1);
        float ly = fminf(y - (float)yl, 1.0f);
        float lx = fminf(x - (float)xl, 1.0f);
        float hy = 1.0f - ly, hx = 1.0f - lx;
        float w1 = hy * hx, w2 = hy * lx, w3 = ly * hx, w4 = ly * lx;
        if (empty) { w1 = w2 = w3 = w4 = 0.0f; }

        // offsets in uint2 (=4 half) units: pixel * CC/4 = pixel * 64
        sm.o[tid] = make_int4((yl * WW + xl) * (CC / 4), (yl * WW + xh) * (CC / 4),
                              (yh * WW + xl) * (CC / 4), (yh * WW + xh) * (CC / 4));
        sm.w[tid] = make_float4(w1, w2, w3, w4);
    }
    if (tid == 0) sm.base_b = (int)r[0];
    __syncthreads();

    // thread owns channels {4*tid .. 4*tid+3}
    const uint2* __restrict__ f =
        g_nhwc2 + (size_t)sm.base_b * (HW * (CC / 4)) + tid;

#pragma unroll 1
    for (int bi = 0; bi < 7; bi++) {
        const int t0 = bi * 4;
        float a0 = 0.f, a1 = 0.f, a2 = 0.f, a3 = 0.f;
#pragma unroll
        for (int q = 0; q < 4; q++) {
            int4   o = sm.o[t0 + q];
            float4 w = sm.w[t0 + q];
            uint2 p1 = __ldg(f + o.x);
            uint2 p2 = __ldg(f + o.y);
            uint2 p3 = __ldg(f + o.z);
            uint2 p4 = __ldg(f + o.w);
            float2 va, vb;
            va = __half22float2(*(__half2*)&p1.x);
            vb = __half22float2(*(__half2*)&p1.y);
            a0 += w.x * va.x; a1 += w.x * va.y;
            a2 += w.x * vb.x; a3 += w.x * vb.y;
            va = __half22float2(*(__half2*)&p2.x);
            vb = __half22float2(*(__half2*)&p2.y);
            a0 += w.y * va.x; a1 += w.y * va.y;
            a2 += w.y * vb.x; a3 += w.y * vb.y;
            va = __half22float2(*(__half2*)&p3.x);
            vb = __half22float2(*(__half2*)&p3.y);
            a0 += w.z * va.x; a1 += w.z * va.y;
            a2 += w.z * vb.x; a3 += w.z * vb.y;
            va = __half22float2(*(__half2*)&p4.x);
            vb = __half22float2(*(__half2*)&p4.y);
            a0 += w.w * va.x; a1 += w.w * va.y;
            a2 += w.w * vb.x; a3 += w.w * vb.y;
        }
        __half2 h01 = __floats2half2_rn(a0 * 0.25f, a1 * 0.25f);
        __half2 h23 = __floats2half2_rn(a2 * 0.25f, a3 * 0.25f);
        uint2 pk;
        pk.x = *(unsigned*)&h01;
        pk.y = *(unsigned*)&h23;
        *((uint2*)&sm.stage[bi][0] + tid) = pk;
    }
    __syncthreads();

    float* __restrict__ o_roi = out + (size_t)n * (CC * NBINS);
    // coalesced flush: consecutive k -> runs of 7 consecutive floats
    for (int k = tid; k < CC * 7; k += TPB) {
        int c  = k / 7;
        int bb = k - c * 7;
        o_roi[c * NBINS + b0 + bb] = __half2float(sm.stage[bb][c]);
    }
}

// ---------------------------------------------------------------------------
extern "C" void kernel_launch(void* const* d_in, const int* in_sizes, int n_in,
                              void* d_out, int out_size) {
    const float* feats = (const float*)d_in[0];  // (2,256,200,304) f32
    const float* rois  = (const float*)d_in[1];  // (N,6) f32
    float* out = (float*)d_out;                  // (N,256,7,7) f32
    int n_rois = in_sizes[1] / 6;

    dim3 tgrid(HW / 64, CC / 64, BB);
    nchw_to_nhwc_h<<<tgrid, 256>>>(feats);

    roi_align_rotated<<<dim3(n_rois, 7), TPB>>>(rois, out);
}

// round 10
// speedup vs baseline: 1.1186x; 1.1186x over previous
#include <cuda_runtime.h>
#include <cuda_fp16.h>
#include <math.h>

#define BB 2
#define CC 256
#define HH 200
#define WW 304
#define HW (HH * WW)            /* 60800 = 64 * 950 exactly */
#define OUTH 7
#define OUTW 7
#define NBINS (OUTH * OUTW)
#define SRR 2
#define SCALE 0.25f
#define NLOC 56                 /* samples needed by one block: 2 chunks x 7 bins x 4 */

// NHWC fp16 scratch as uint2 so 8-byte gathers are guaranteed aligned.
// (B, H, W, C) halves = 62.3 MB (L2-resident).
__device__ uint2 g_nhwc2[(size_t)BB * HW * (CC / 4)];

// ---------------------------------------------------------------------------
// Kernel 1: NCHW f32 -> NHWC fp16. Tile 64 ch x 64 hw, 256 threads.
// HW = 64*950 exactly -> no bounds checks. float4 global reads (LDG.128),
// uint4 packed writes (8 channels = 16B).
// ---------------------------------------------------------------------------
__global__ __launch_bounds__(256) void nchw_to_nhwc_h(const float* __restrict__ in) {
    __shared__ float tile[64 * 65];
    const int b   = blockIdx.z;
    const int hw0 = blockIdx.x * 64;
    const int c0  = blockIdx.y * 64;
    const int t   = threadIdx.x;       // 0..255

    const int x  = t & 15;             // 16 float4 = 64 hw
    const int cr = t >> 4;             // 0..15
    const float* src = in + (size_t)b * CC * HW + (size_t)(c0 + cr) * HW + hw0 + 4 * x;
#pragma unroll
    for (int i = 0; i < 4; i++) {
        float4 v = *(const float4*)(src + (size_t)(16 * i) * HW);
        float* dst = &tile[(cr + 16 * i) * 65 + 4 * x];
        dst[0] = v.x; dst[1] = v.y; dst[2] = v.z; dst[3] = v.w;
    }
    __syncthreads();

    __half2* outh = (__half2*)g_nhwc2 + (size_t)b * HW * (CC / 2);
#pragma unroll
    for (int i = 0; i < 2; i++) {
        int w  = t + 256 * i;
        int hw = w >> 3;               // 0..63
        int cg = w & 7;                // 8-channel group
        const float* col = &tile[(cg * 8) * 65 + hw];
        uint4 pk;
        __half2 h;
        h = __floats2half2_rn(col[0 * 65], col[1 * 65]); pk.x = *(unsigned*)&h;
        h = __floats2half2_rn(col[2 * 65], col[3 * 65]); pk.y = *(unsigned*)&h;
        h = __floats2half2_rn(col[4 * 65], col[5 * 65]); pk.z = *(unsigned*)&h;
        h = __floats2half2_rn(col[6 * 65], col[7 * 65]); pk.w = *(unsigned*)&h;
        *(uint4*)(outh + ((size_t)(hw0 + hw) * CC + c0) / 2 + cg * 4) = pk;
    }
}

// ---------------------------------------------------------------------------
// Kernel 2: rotated ROI align on fp16 NHWC  (R7 configuration — proven best).
// Grid (n_rois, 4), block 128 = 2 subgroups of 64 threads; subgroup handles
// ONE 7-bin chunk (chunk = 2*y+sub, chunk 7 idles). Setup computes only the
// 56 samples this block needs (__sincosf). 0.25 averaging folded into the
// weights. 4 ch/thread via uint2 (8B) gathers, f32 FMA inner loop, fp16
// stage, coalesced f32 flush. smem ~9.3KB, 12 blocks/SM.
// ---------------------------------------------------------------------------
#define TPB 128

struct AlignSmem {
    int4   o[NLOC];              // 4 corner offsets in uint2 units (pix*64)
    float4 w[NLOC];              // 4 bilinear weights * 0.25 (zeroed if empty)
    __half stage[2][7][264];     // [subgroup][bin-in-chunk][channel(+pad)]
    int    base_b;
};

__global__ __launch_bounds__(TPB, 12) void roi_align_rotated(
    const float* __restrict__ rois, float* __restrict__ out) {
    __shared__ AlignSmem sm;
    const int n   = blockIdx.x;
    const int tid = threadIdx.x;
    const int sub = tid >> 6;        // 0/1: chunk subgroup
    const int lt  = tid & 63;        // channel-group lane
    const float* r = rois + (size_t)n * 6;

    if (tid < NLOC) {
        // local sample t -> (sub, bin-in-chunk, iy, ix)
        const int tsub = tid / 28;
        const int rest = tid - tsub * 28;
        const int bi   = rest >> 2;
        const int iy   = (rest >> 1) & 1;
        const int ix   = rest & 1;
        const int bin  = 7 * (2 * blockIdx.y + tsub) + bi;   // may be >=49 (unused)
        const int ph   = bin / OUTW;
        const int pw   = bin - ph * OUTW;
        const int i = ph * SRR + iy;      // y sample index
        const int j = pw * SRR + ix;      // x sample index

        float cw = r[1] * SCALE - 0.5f;
        float ch = r[2] * SCALE - 0.5f;
        float rw = r[3] * SCALE;
        float rh = r[4] * SCALE;
        float theta = r[5] * (float)(M_PI / 180.0);
        float st, ct;
        __sincosf(theta, &st, &ct);

        float bin_h = rh * (1.0f / OUTH);
        float bin_w = rw * (1.0f / OUTW);
        float ty = (i + 0.5f) * (1.0f / SRR);
        float tx = (j + 0.5f) * (1.0f / SRR);
        float yy = -rh * 0.5f + ty * bin_h;
        float xx = -rw * 0.5f + tx * bin_w;
        float y = yy * ct - xx * st + ch;
        float x = yy * st + xx * ct + cw;

        bool empty = (y < -1.0f) | (y > (float)HH) | (x < -1.0f) | (x > (float)WW);
        y = fmaxf(y, 0.0f);
        x = fmaxf(x, 0.0f);
        int yl = min((int)floorf(y), HH - 1);
        int xl = min((int)floorf(x), WW - 1);
        int yh = min(yl + 1, HH - 1);
        int xh = min(xl + 1, WW - 1);
        float ly = fminf(y - (float)yl, 1.0f);
        float lx = fminf(x - (float)xl, 1.0f);
        float hy = 1.0f - ly, hx = 1.0f - lx;
        // fold the 1/16-sample -> *0.25 per 4-sample-bin average into weights
        float w1 = 0.25f * hy * hx, w2 = 0.25f * hy * lx;
        float w3 = 0.25f * ly * hx, w4 = 0.25f * ly * lx;
        if (empty) { w1 = w2 = w3 = w4 = 0.0f; }

        // offsets in uint2 (=4 half) units: pixel * CC/4 = pixel * 64
        sm.o[tid] = make_int4((yl * WW + xl) * (CC / 4), (yl * WW + xh) * (CC / 4),
                              (yh * WW + xl) * (CC / 4), (yh * WW + xh) * (CC / 4));
        sm.w[tid] = make_float4(w1, w2, w3, w4);
    }
    if (tid == 0) sm.base_b = (int)r[0];
    __syncthreads();

    const int chunk = 2 * blockIdx.y + sub;      // 0..7
    const int b0 = 7 * chunk;
    const int live = (b0 < NBINS);               // chunk 7 idles

    if (live) {
        // thread owns channels {4lt .. 4lt+3}
        const uint2* __restrict__ f =
            g_nhwc2 + (size_t)sm.base_b * (HW * (CC / 4)) + lt;

#pragma unroll 1
        for (int bi = 0; bi < 7; bi++) {
            const int t0 = sub * 28 + bi * 4;
            float a0 = 0.f, a1 = 0.f, a2 = 0.f, a3 = 0.f;
#pragma unroll
            for (int q = 0; q < 4; q++) {
                int4   o = sm.o[t0 + q];
                float4 w = sm.w[t0 + q];
                uint2 p1 = __ldg(f + o.x);
                uint2 p2 = __ldg(f + o.y);
                uint2 p3 = __ldg(f + o.z);
                uint2 p4 = __ldg(f + o.w);
                float2 va, vb;
                va = __half22float2(*(__half2*)&p1.x);
                vb = __half22float2(*(__half2*)&p1.y);
                a0 += w.x * va.x; a1 += w.x * va.y;
                a2 += w.x * vb.x; a3 += w.x * vb.y;
                va = __half22float2(*(__half2*)&p2.x);
                vb = __half22float2(*(__half2*)&p2.y);
                a0 += w.y * va.x; a1 += w.y * va.y;
                a2 += w.y * vb.x; a3 += w.y * vb.y;
                va = __half22float2(*(__half2*)&p3.x);
                vb = __half22float2(*(__half2*)&p3.y);
                a0 += w.z * va.x; a1 += w.z * va.y;
                a2 += w.z * vb.x; a3 += w.z * vb.y;
                va = __half22float2(*(__half2*)&p4.x);
                vb = __half22float2(*(__half2*)&p4.y);
                a0 += w.w * va.x; a1 += w.w * va.y;
                a2 += w.w * vb.x; a3 += w.w * vb.y;
            }
            __half2 h01 = __floats2half2_rn(a0, a1);
            __half2 h23 = __floats2half2_rn(a2, a3);
            uint2 pk;
            pk.x = *(unsigned*)&h01;
            pk.y = *(unsigned*)&h23;
            *((uint2*)&sm.stage[sub][bi][0] + lt) = pk;
        }
    }
    __syncthreads();
    if (live) {
        float* __restrict__ o_roi = out + (size_t)n * (CC * NBINS);
        // coalesced flush: consecutive k -> runs of 7 consecutive floats
        for (int k = lt; k < CC * 7; k += 64) {
            int c  = k / 7;
            int bb = k - c * 7;
            o_roi[c * NBINS + b0 + bb] = __half2float(sm.stage[sub][bb][c]);
        }
    }
}

// ---------------------------------------------------------------------------
extern "C" void kernel_launch(void* const* d_in, const int* in_sizes, int n_in,
                              void* d_out, int out_size) {
    const float* feats = (const float*)d_in[0];  // (2,256,200,304) f32
    const float* rois  = (const float*)d_in[1];  // (N,6) f32
    float* out = (float*)d_out;                  // (N,256,7,7) f32
    int n_rois = in_sizes[1] / 6;

    dim3 tgrid(HW / 64, CC / 64, BB);
    nchw_to_nhwc_h<<<tgrid, 256>>>(feats);

    roi_align_rotated<<<dim3(n_rois, 4), TPB>>>(rois, out);
}

// round 11
// speedup vs baseline: 1.1226x; 1.0036x over previous
#include <cuda_runtime.h>
#include <cuda_fp16.h>
#include <math.h>

#define BB 2
#define CC 256
#define HH 200
#define WW 304
#define HW (HH * WW)            /* 60800 = 64 * 950 exactly */
#define OUTH 7
#define OUTW 7
#define NBINS (OUTH * OUTW)
#define SRR 2
#define SCALE 0.25f
#define NLOC 56                 /* samples needed by one block: 2 chunks x 7 bins x 4 */

// NHWC fp16 scratch as uint2 so 8-byte gathers are guaranteed aligned.
// (B, H, W, C) halves = 62.3 MB (L2-resident).
__device__ uint2 g_nhwc2[(size_t)BB * HW * (CC / 4)];

// ---------------------------------------------------------------------------
// Kernel 1: NCHW f32 -> NHWC fp16. Tile 64 ch x 64 hw, 256 threads.
// HW = 64*950 exactly -> no bounds checks. float4 global reads (LDG.128),
// uint4 packed writes (8 channels = 16B).
// ---------------------------------------------------------------------------
__global__ __launch_bounds__(256) void nchw_to_nhwc_h(const float* __restrict__ in) {
    __shared__ float tile[64 * 65];
    const int b   = blockIdx.z;
    const int hw0 = blockIdx.x * 64;
    const int c0  = blockIdx.y * 64;
    const int t   = threadIdx.x;       // 0..255

    const int x  = t & 15;             // 16 float4 = 64 hw
    const int cr = t >> 4;             // 0..15
    const float* src = in + (size_t)b * CC * HW + (size_t)(c0 + cr) * HW + hw0 + 4 * x;
#pragma unroll
    for (int i = 0; i < 4; i++) {
        float4 v = *(const float4*)(src + (size_t)(16 * i) * HW);
        float* dst = &tile[(cr + 16 * i) * 65 + 4 * x];
        dst[0] = v.x; dst[1] = v.y; dst[2] = v.z; dst[3] = v.w;
    }
    __syncthreads();

    __half2* outh = (__half2*)g_nhwc2 + (size_t)b * HW * (CC / 2);
#pragma unroll
    for (int i = 0; i < 2; i++) {
        int w  = t + 256 * i;
        int hw = w >> 3;               // 0..63
        int cg = w & 7;                // 8-channel group
        const float* col = &tile[(cg * 8) * 65 + hw];
        uint4 pk;
        __half2 h;
        h = __floats2half2_rn(col[0 * 65], col[1 * 65]); pk.x = *(unsigned*)&h;
        h = __floats2half2_rn(col[2 * 65], col[3 * 65]); pk.y = *(unsigned*)&h;
        h = __floats2half2_rn(col[4 * 65], col[5 * 65]); pk.z = *(unsigned*)&h;
        h = __floats2half2_rn(col[6 * 65], col[7 * 65]); pk.w = *(unsigned*)&h;
        *(uint4*)(outh + ((size_t)(hw0 + hw) * CC + c0) / 2 + cg * 4) = pk;
    }
}

// ---------------------------------------------------------------------------
// Kernel 2: rotated ROI align on fp16 NHWC.
// Grid (n_rois, 4), block 128 = 2 subgroups of 64 threads; subgroup handles
// ONE 7-bin chunk (chunk = 2*y+sub, chunk 7 idles). Setup computes only the
// 56 samples this block needs. Per bin: issue ALL 16 corner gathers first
// (MLP=16/warp), then convert+FMA consuming weights from smem. f32 accum,
// 0.25 folded into weights, fp16 stage, coalesced f32 flush.
// ---------------------------------------------------------------------------
#define TPB 128

struct AlignSmem {
    int4   o[NLOC];              // 4 corner offsets in uint2 units (pix*64)
    float4 w[NLOC];              // 4 bilinear weights * 0.25 (zeroed if empty)
    __half stage[2][7][264];     // [subgroup][bin-in-chunk][channel(+pad)]
    int    base_b;
};

__global__ __launch_bounds__(TPB, 10) void roi_align_rotated(
    const float* __restrict__ rois, float* __restrict__ out) {
    __shared__ AlignSmem sm;
    const int n   = blockIdx.x;
    const int tid = threadIdx.x;
    const int sub = tid >> 6;        // 0/1: chunk subgroup
    const int lt  = tid & 63;        // channel-group lane
    const float* r = rois + (size_t)n * 6;

    if (tid < NLOC) {
        // local sample t -> (sub, bin-in-chunk, iy, ix)
        const int tsub = tid / 28;
        const int rest = tid - tsub * 28;
        const int bi   = rest >> 2;
        const int iy   = (rest >> 1) & 1;
        const int ix   = rest & 1;
        const int bin  = 7 * (2 * blockIdx.y + tsub) + bi;   // may be >=49 (unused)
        const int ph   = bin / OUTW;
        const int pw   = bin - ph * OUTW;
        const int i = ph * SRR + iy;      // y sample index
        const int j = pw * SRR + ix;      // x sample index

        float cw = r[1] * SCALE - 0.5f;
        float ch = r[2] * SCALE - 0.5f;
        float rw = r[3] * SCALE;
        float rh = r[4] * SCALE;
        float theta = r[5] * (float)(M_PI / 180.0);
        float st, ct;
        __sincosf(theta, &st, &ct);

        float bin_h = rh * (1.0f / OUTH);
        float bin_w = rw * (1.0f / OUTW);
        float ty = (i + 0.5f) * (1.0f / SRR);
        float tx = (j + 0.5f) * (1.0f / SRR);
        float yy = -rh * 0.5f + ty * bin_h;
        float xx = -rw * 0.5f + tx * bin_w;
        float y = yy * ct - xx * st + ch;
        float x = yy * st + xx * ct + cw;

        bool empty = (y < -1.0f) | (y > (float)HH) | (x < -1.0f) | (x > (float)WW);
        y = fmaxf(y, 0.0f);
        x = fmaxf(x, 0.0f);
        int yl = min((int)floorf(y), HH - 1);
        int xl = min((int)floorf(x), WW - 1);
        int yh = min(yl + 1, HH - 1);
        int xh = min(xl + 1, WW - 1);
        float ly = fminf(y - (float)yl, 1.0f);
        float lx = fminf(x - (float)xl, 1.0f);
        float hy = 1.0f - ly, hx = 1.0f - lx;
        // fold the bin's 4-sample average (*0.25) into the weights
        float w1 = 0.25f * hy * hx, w2 = 0.25f * hy * lx;
        float w3 = 0.25f * ly * hx, w4 = 0.25f * ly * lx;
        if (empty) { w1 = w2 = w3 = w4 = 0.0f; }

        // offsets in uint2 (=4 half) units: pixel * CC/4 = pixel * 64
        sm.o[tid] = make_int4((yl * WW + xl) * (CC / 4), (yl * WW + xh) * (CC / 4),
                              (yh * WW + xl) * (CC / 4), (yh * WW + xh) * (CC / 4));
        sm.w[tid] = make_float4(w1, w2, w3, w4);
    }
    if (tid == 0) sm.base_b = (int)r[0];
    __syncthreads();

    const int chunk = 2 * blockIdx.y + sub;      // 0..7
    const int b0 = 7 * chunk;
    const int live = (b0 < NBINS);               // chunk 7 idles

    if (live) {
        // thread owns channels {4lt .. 4lt+3}
        const uint2* __restrict__ f =
            g_nhwc2 + (size_t)sm.base_b * (HW * (CC / 4)) + lt;

#pragma unroll 1
        for (int bi = 0; bi < 7; bi++) {
            const int t0 = sub * 28 + bi * 4;

            // ---- phase 1: issue all 16 gathers (max MLP) ----
            uint2 p[16];
#pragma unroll
            for (int q = 0; q < 4; q++) {
                int4 o = sm.o[t0 + q];
                p[4 * q + 0] = __ldg(f + o.x);
                p[4 * q + 1] = __ldg(f + o.y);
                p[4 * q + 2] = __ldg(f + o.z);
                p[4 * q + 3] = __ldg(f + o.w);
            }

            // ---- phase 2: convert + FMA (weights re-read from smem) ----
            float a0 = 0.f, a1 = 0.f, a2 = 0.f, a3 = 0.f;
#pragma unroll
            for (int q = 0; q < 4; q++) {
                float4 w = sm.w[t0 + q];
                float2 va, vb;
                va = __half22float2(*(__half2*)&p[4 * q + 0].x);
                vb = __half22float2(*(__half2*)&p[4 * q + 0].y);
                a0 += w.x * va.x; a1 += w.x * va.y;
                a2 += w.x * vb.x; a3 += w.x * vb.y;
                va = __half22float2(*(__half2*)&p[4 * q + 1].x);
                vb = __half22float2(*(__half2*)&p[4 * q + 1].y);
                a0 += w.y * va.x; a1 += w.y * va.y;
                a2 += w.y * vb.x; a3 += w.y * vb.y;
                va = __half22float2(*(__half2*)&p[4 * q + 2].x);
                vb = __half22float2(*(__half2*)&p[4 * q + 2].y);
                a0 += w.z * va.x; a1 += w.z * va.y;
                a2 += w.z * vb.x; a3 += w.z * vb.y;
                va = __half22float2(*(__half2*)&p[4 * q + 3].x);
                vb = __half22float2(*(__half2*)&p[4 * q + 3].y);
                a0 += w.w * va.x; a1 += w.w * va.y;
                a2 += w.w * vb.x; a3 += w.w * vb.y;
            }
            __half2 h01 = __floats2half2_rn(a0, a1);
            __half2 h23 = __floats2half2_rn(a2, a3);
            uint2 pk;
            pk.x = *(unsigned*)&h01;
            pk.y = *(unsigned*)&h23;
            *((uint2*)&sm.stage[sub][bi][0] + lt) = pk;
        }
    }
    __syncthreads();
    if (live) {
        float* __restrict__ o_roi = out + (size_t)n * (CC * NBINS);
        // coalesced flush: consecutive k -> runs of 7 consecutive floats
        for (int k = lt; k < CC * 7; k += 64) {
            int c  = k / 7;
            int bb = k - c * 7;
            o_roi[c * NBINS + b0 + bb] = __half2float(sm.stage[sub][bb][c]);
        }
    }
}

// ---------------------------------------------------------------------------
extern "C" void kernel_launch(void* const* d_in, const int* in_sizes, int n_in,
                              void* d_out, int out_size) {
    const float* feats = (const float*)d_in[0];  // (2,256,200,304) f32
    const float* rois  = (const float*)d_in[1];  // (N,6) f32
    float* out = (float*)d_out;                  // (N,256,7,7) f32
    int n_rois = in_sizes[1] / 6;

    dim3 tgrid(HW / 64, CC / 64, BB);
    nchw_to_nhwc_h<<<tgrid, 256>>>(feats);

    roi_align_rotated<<<dim3(n_rois, 4), TPB>>>(rois, out);
}